// round 10
// baseline (speedup 1.0000x reference)
#include <cuda_runtime.h>
#include <cstdint>
#include <math_constants.h>

#define NHEADS 32
#define HD     128
#define NB     2
#define NS     2048
#define NH     4096
#define NTOK   (NB*NS)   // 4096 tokens
#define QSCALE 0.08838834764831845f   // 1/sqrt(128)

// ---------------- scratch (device globals: no allocations allowed) ----------
__device__ float g_q[(size_t)NB*NHEADS*NS*HD];    // [b][h][s][d]  (pre-scaled+rounded)
__device__ float g_k[(size_t)NB*NHEADS*NS*HD];    // rounded
__device__ float g_v[(size_t)NB*NHEADS*NS*HD];    // rounded
__device__ float g_ctx[(size_t)NTOK*NH];          // token-major, rounded
__device__ float g_xr[(size_t)NTOK*NH];           // rounded x
__device__ float g_wqkvr[(size_t)NH*3*NH];        // rounded W_qkv [K][N]
__device__ float g_wor[(size_t)NH*NH];            // rounded W_o   [K][N]

// ---------------- helpers ----------------------------------------------------
__device__ __forceinline__ float tf32f(float x) {
    unsigned u; asm("cvt.rna.tf32.f32 %0, %1;" : "=r"(u) : "f"(x));
    return __uint_as_float(u);
}

__device__ __forceinline__ void mma8(float* d, const unsigned* a, const unsigned* b) {
    asm volatile(
        "mma.sync.aligned.m16n8k8.row.col.f32.tf32.tf32.f32 "
        "{%0,%1,%2,%3}, {%4,%5,%6,%7}, {%8,%9}, {%0,%1,%2,%3};\n"
        : "+f"(d[0]), "+f"(d[1]), "+f"(d[2]), "+f"(d[3])
        : "r"(a[0]), "r"(a[1]), "r"(a[2]), "r"(a[3]), "r"(b[0]), "r"(b[1]));
}

__device__ __forceinline__ void ldsm4(unsigned* r, unsigned addr) {
    asm volatile("ldmatrix.sync.aligned.m8n8.x4.shared.b16 {%0,%1,%2,%3}, [%4];"
        : "=r"(r[0]), "=r"(r[1]), "=r"(r[2]), "=r"(r[3]) : "r"(addr));
}

#define CP_ASYNC16(saddr, gptr) \
    asm volatile("cp.async.cg.shared.global [%0], [%1], 16;" :: "r"(saddr), "l"(gptr))
#define CP_COMMIT() asm volatile("cp.async.commit_group;" ::: "memory")
#define CP_WAIT1()  asm volatile("cp.async.wait_group 1;" ::: "memory")

__device__ __forceinline__ unsigned smem_u32(const void* p) {
    unsigned a;
    asm("{ .reg .u64 t; cvta.to.shared.u64 t, %1; cvt.u32.u64 %0, t; }" : "=r"(a) : "l"(p));
    return a;
}

// ---------------- pre-round: dst = tf32(src), vectorized ---------------------
__global__ void round_copy(const float* __restrict__ src, float* __restrict__ dst, int n4) {
    int stride = gridDim.x * blockDim.x;
    for (int i = blockIdx.x * blockDim.x + threadIdx.x; i < n4; i += stride) {
        float4 v = ((const float4*)src)[i];
        v.x = tf32f(v.x); v.y = tf32f(v.y); v.z = tf32f(v.z); v.w = tf32f(v.w);
        ((float4*)dst)[i] = v;
    }
}

__device__ __forceinline__ void scatter_qkv(int m, int n, float v) {
    int b = m >> 11, s = m & 2047;
    int which = n >> 12, rem = n & 4095;
    int h = rem >> 7, d = rem & 127;
    size_t idx = ((((size_t)b * NHEADS + h) * NS) + s) * HD + d;
    if (which == 0)      g_q[idx] = tf32f(v * QSCALE);
    else if (which == 1) g_k[idx] = tf32f(v);
    else                 g_v[idx] = tf32f(v);
}

// =============================================================================
// GEMM: C[M,N] = A[M,K] @ W[K,N] + bias.  Operands PRE-ROUNDED to tf32.
// CTA 128x128, ktile 32, 128 threads = 4 warps, warp tile 64x64.
// 2-stage cp.async pipeline, 71680 B smem -> 2 CTAs/SM (8 warps: fills
// sync/wait bubbles that capped tensor pipe at 70% with 1 CTA/SM).
// A-fragments: ldmatrix.x4 (conflict-free, row stride 144B).
// B-fragments: 2x LDS.32, conflict-free.
// =============================================================================
#define STG_F 8960          // floats per stage
#define GEMM_SMEM (2 * STG_F * 4)

template<int MODE>
__global__ __launch_bounds__(128, 2) void gemm_tf32(
    const float* __restrict__ bias, float* __restrict__ C, int M, int N, int K)
{
    extern __shared__ float dsm[];
    const unsigned sbase = smem_u32(dsm);

    const int tid  = threadIdx.x;
    const int warp = tid >> 5, lane = tid & 31;
    const int wm = warp >> 1, wn = warp & 1;
    const int lq = lane & 3, lr = lane >> 2;
    const int brow = blockIdx.y * 128, bcol = blockIdx.x * 128;

    const float* gA = ((MODE == 0) ? g_xr : g_ctx) + (size_t)brow * K;
    const float* gB = ((MODE == 0) ? g_wqkvr : g_wor) + bcol;

    const int aRow = tid >> 3, aC = tid & 7;
    const int bRow = tid >> 5, bC = tid & 31;

    const int ntiles = K >> 5;

    auto issue = [&](int kt) {
        if (kt < ntiles) {
            const int st = kt & 1;
            const unsigned sA = sbase + st * (STG_F * 4);
            const unsigned sB = sA + 4608 * 4;
            const float* ga = gA + kt * 32;
            #pragma unroll
            for (int i = 0; i < 8; i++) {
                int row = aRow + 16 * i;
                CP_ASYNC16(sA + (row * 36 + aC * 4) * 4, ga + (size_t)row * K + aC * 4);
            }
            const float* gb = gB + (size_t)kt * 32 * N;
            #pragma unroll
            for (int i = 0; i < 8; i++) {
                int row = bRow + 4 * i;
                CP_ASYNC16(sB + (row * 136 + bC * 4) * 4, gb + (size_t)row * N + bC * 4);
            }
        }
        CP_COMMIT();
    };

    float acc[4][8][4];
    #pragma unroll
    for (int mi = 0; mi < 4; mi++)
        #pragma unroll
        for (int ni = 0; ni < 8; ni++)
            #pragma unroll
            for (int j = 0; j < 4; j++) acc[mi][ni][j] = 0.f;

    issue(0); issue(1);

    const int aLdsmOff = (lane & 15) * 36 + ((lane >> 4) << 2);

    for (int kt = 0; kt < ntiles; kt++) {
        CP_WAIT1();
        __syncthreads();             // stage kt fully landed, visible to all warps
        const int st = kt & 1;
        const unsigned aBase = sbase + st * (STG_F * 4);
        const float* sB = dsm + st * STG_F + 4608;

        #pragma unroll
        for (int ks = 0; ks < 4; ks++) {
            unsigned af[4][4];
            #pragma unroll
            for (int mi = 0; mi < 4; mi++)
                ldsm4(af[mi], aBase + ((wm * 64 + mi * 16) * 36 + ks * 8 + aLdsmOff) * 4);
            float bf[8][2];
            const float* bp = sB + (ks * 8 + lq) * 136 + wn * 64 + lr;
            #pragma unroll
            for (int ni = 0; ni < 8; ni++) {
                bf[ni][0] = bp[ni * 8];
                bf[ni][1] = bp[ni * 8 + 4 * 136];
            }
            #pragma unroll
            for (int ni = 0; ni < 8; ni++)
                #pragma unroll
                for (int mi = 0; mi < 4; mi++)
                    mma8(acc[mi][ni], af[mi], (const unsigned*)bf[ni]);
        }
        __syncthreads();             // all warps done reading slot kt&1
        issue(kt + 2);               // safe to overwrite it
    }

    #pragma unroll
    for (int mi = 0; mi < 4; mi++) {
        int r0 = brow + wm * 64 + mi * 16 + lr;
        #pragma unroll
        for (int ni = 0; ni < 8; ni++) {
            int c0 = bcol + wn * 64 + ni * 8 + 2 * lq;
            float v0 = acc[mi][ni][0] + bias[c0];
            float v1 = acc[mi][ni][1] + bias[c0 + 1];
            float v2 = acc[mi][ni][2] + bias[c0];
            float v3 = acc[mi][ni][3] + bias[c0 + 1];
            if (MODE == 0) {
                scatter_qkv(r0,     c0,     v0);
                scatter_qkv(r0,     c0 + 1, v1);
                scatter_qkv(r0 + 8, c0,     v2);
                scatter_qkv(r0 + 8, c0 + 1, v3);
            } else {
                C[(size_t)r0 * N + c0]           = v0;
                C[(size_t)r0 * N + c0 + 1]       = v1;
                C[(size_t)(r0 + 8) * N + c0]     = v2;
                C[(size_t)(r0 + 8) * N + c0 + 1] = v3;
            }
        }
    }
}

// =============================================================================
// Flash attention (round-7, unchanged): CTA = 256 q-rows, 8 warps, warp = 32
// rows; register-resident P via quad shuffles; ldmatrix Q a-frags.
// =============================================================================
#define FQ_STRIDE 132
#define FK_STRIDE 132
#define FV_STRIDE 136
#define SM_FK (256 * FQ_STRIDE)
#define SM_FV (SM_FK + 64 * FK_STRIDE)
#define SMEM_FLASH ((SM_FV + 64 * FV_STRIDE) * 4)

__global__ __launch_bounds__(256, 1) void flash_attn()
{
    extern __shared__ float sm[];
    float* Qs = sm;
    float* Ks = sm + SM_FK;
    float* Vs = sm + SM_FV;
    const unsigned qbase = smem_u32(sm);

    const int tid = threadIdx.x, w = tid >> 5, lane = tid & 31;
    const int lq = lane & 3, lr = lane >> 2;
    const int bh = blockIdx.y, qt = blockIdx.x;

    const float* Qg = g_q + ((size_t)bh * NS + qt * 256) * HD;
    const float* Kg = g_k + (size_t)bh * NS * HD;
    const float* Vg = g_v + (size_t)bh * NS * HD;

    #pragma unroll
    for (int i = 0; i < 32; i++) {
        int f = tid + i * 256;
        int row = f >> 5, c4 = (f & 31) << 2;
        *(float4*)(Qs + row * FQ_STRIDE + c4) = *(const float4*)(Qg + (size_t)row * HD + c4);
    }

    float oacc[2][16][4];
    #pragma unroll
    for (int mi = 0; mi < 2; mi++)
        #pragma unroll
        for (int nt = 0; nt < 16; nt++)
            #pragma unroll
            for (int j = 0; j < 4; j++) oacc[mi][nt][j] = 0.f;

    float mrow[2][2], lrow[2][2];
    #pragma unroll
    for (int mi = 0; mi < 2; mi++) {
        mrow[mi][0] = -CUDART_INF_F; mrow[mi][1] = -CUDART_INF_F;
        lrow[mi][0] = 0.f;           lrow[mi][1] = 0.f;
    }

    const int aOff0 = (w * 32 + (lane & 15)) * FQ_STRIDE + ((lane >> 4) << 2);
    const int psrc0 = (lane & ~3) | (lq >> 1);
    const int psrc1 = psrc0 + 2;
    const bool podd = (lq & 1);

    for (int kt = 0; kt < NS / 64; kt++) {
        __syncthreads();
        #pragma unroll
        for (int i = 0; i < 8; i++) {
            int f = tid + i * 256;
            int row = f >> 5, c4 = (f & 31) << 2;
            *(float4*)(Ks + row * FK_STRIDE + c4) =
                *(const float4*)(Kg + (size_t)(kt * 64 + row) * HD + c4);
            *(float4*)(Vs + row * FV_STRIDE + c4) =
                *(const float4*)(Vg + (size_t)(kt * 64 + row) * HD + c4);
        }
        __syncthreads();

        float sacc[2][8][4];
        #pragma unroll
        for (int mi = 0; mi < 2; mi++)
            #pragma unroll
            for (int ni = 0; ni < 8; ni++)
                #pragma unroll
                for (int j = 0; j < 4; j++) sacc[mi][ni][j] = 0.f;

        #pragma unroll
        for (int ks = 0; ks < 16; ks++) {
            unsigned af[2][4];
            ldsm4(af[0], qbase + (aOff0 + ks * 8) * 4);
            ldsm4(af[1], qbase + (aOff0 + 16 * FQ_STRIDE + ks * 8) * 4);
            const float* kp = Ks + lr * FK_STRIDE + ks * 8 + lq;
            #pragma unroll
            for (int ni = 0; ni < 8; ni++) {
                unsigned kb[2];
                kb[0] = __float_as_uint(kp[ni * 8 * FK_STRIDE]);
                kb[1] = __float_as_uint(kp[ni * 8 * FK_STRIDE + 4]);
                mma8(sacc[0][ni], af[0], kb);
                mma8(sacc[1][ni], af[1], kb);
            }
        }

        #pragma unroll
        for (int mi = 0; mi < 2; mi++) {
            float mt0 = -CUDART_INF_F, mt1 = -CUDART_INF_F;
            #pragma unroll
            for (int ni = 0; ni < 8; ni++) {
                mt0 = fmaxf(mt0, fmaxf(sacc[mi][ni][0], sacc[mi][ni][1]));
                mt1 = fmaxf(mt1, fmaxf(sacc[mi][ni][2], sacc[mi][ni][3]));
            }
            mt0 = fmaxf(mt0, __shfl_xor_sync(0xffffffffu, mt0, 1));
            mt0 = fmaxf(mt0, __shfl_xor_sync(0xffffffffu, mt0, 2));
            mt1 = fmaxf(mt1, __shfl_xor_sync(0xffffffffu, mt1, 1));
            mt1 = fmaxf(mt1, __shfl_xor_sync(0xffffffffu, mt1, 2));

            float mn0 = fmaxf(mrow[mi][0], mt0), mn1 = fmaxf(mrow[mi][1], mt1);
            float a0 = __expf(mrow[mi][0] - mn0), a1 = __expf(mrow[mi][1] - mn1);

            float sum0 = 0.f, sum1 = 0.f;
            #pragma unroll
            for (int ni = 0; ni < 8; ni++) {
                sacc[mi][ni][0] = __expf(sacc[mi][ni][0] - mn0);
                sacc[mi][ni][1] = __expf(sacc[mi][ni][1] - mn0);
                sacc[mi][ni][2] = __expf(sacc[mi][ni][2] - mn1);
                sacc[mi][ni][3] = __expf(sacc[mi][ni][3] - mn1);
                sum0 += sacc[mi][ni][0] + sacc[mi][ni][1];
                sum1 += sacc[mi][ni][2] + sacc[mi][ni][3];
            }
            sum0 += __shfl_xor_sync(0xffffffffu, sum0, 1);
            sum0 += __shfl_xor_sync(0xffffffffu, sum0, 2);
            sum1 += __shfl_xor_sync(0xffffffffu, sum1, 1);
            sum1 += __shfl_xor_sync(0xffffffffu, sum1, 2);

            lrow[mi][0] = lrow[mi][0] * a0 + sum0;
            lrow[mi][1] = lrow[mi][1] * a1 + sum1;
            mrow[mi][0] = mn0; mrow[mi][1] = mn1;

            #pragma unroll
            for (int nt = 0; nt < 16; nt++) {
                oacc[mi][nt][0] *= a0; oacc[mi][nt][1] *= a0;
                oacc[mi][nt][2] *= a1; oacc[mi][nt][3] *= a1;
            }
        }

        #pragma unroll
        for (int ks = 0; ks < 8; ks++) {
            unsigned pa[2][4];
            #pragma unroll
            for (int mi = 0; mi < 2; mi++) {
                float y0 = __shfl_sync(0xffffffffu, sacc[mi][ks][0], psrc0);
                float y1 = __shfl_sync(0xffffffffu, sacc[mi][ks][1], psrc0);
                float y2 = __shfl_sync(0xffffffffu, sacc[mi][ks][2], psrc0);
                float y3 = __shfl_sync(0xffffffffu, sacc[mi][ks][3], psrc0);
                float z0 = __shfl_sync(0xffffffffu, sacc[mi][ks][0], psrc1);
                float z1 = __shfl_sync(0xffffffffu, sacc[mi][ks][1], psrc1);
                float z2 = __shfl_sync(0xffffffffu, sacc[mi][ks][2], psrc1);
                float z3 = __shfl_sync(0xffffffffu, sacc[mi][ks][3], psrc1);
                pa[mi][0] = __float_as_uint(tf32f(podd ? y1 : y0));
                pa[mi][1] = __float_as_uint(tf32f(podd ? y3 : y2));
                pa[mi][2] = __float_as_uint(tf32f(podd ? z1 : z0));
                pa[mi][3] = __float_as_uint(tf32f(podd ? z3 : z2));
            }
            const float* vp = Vs + (ks * 8 + lq) * FV_STRIDE + lr;
            #pragma unroll
            for (int nt = 0; nt < 16; nt++) {
                unsigned vb[2];
                vb[0] = __float_as_uint(vp[nt * 8]);
                vb[1] = __float_as_uint(vp[nt * 8 + 4 * FV_STRIDE]);
                mma8(oacc[0][nt], pa[0], vb);
                mma8(oacc[1][nt], pa[1], vb);
            }
        }
    }

    int b = bh >> 5, h = bh & 31;
    #pragma unroll
    for (int mi = 0; mi < 2; mi++) {
        float inv0 = 1.f / lrow[mi][0], inv1 = 1.f / lrow[mi][1];
        int r0 = qt * 256 + w * 32 + mi * 16 + lr;
        size_t tok0 = ((size_t)b * NS + r0) * NH;
        size_t tok1 = ((size_t)b * NS + r0 + 8) * NH;
        #pragma unroll
        for (int nt = 0; nt < 16; nt++) {
            int col = h * HD + nt * 8 + 2 * lq;
            g_ctx[tok0 + col]     = tf32f(oacc[mi][nt][0] * inv0);
            g_ctx[tok0 + col + 1] = tf32f(oacc[mi][nt][1] * inv0);
            g_ctx[tok1 + col]     = tf32f(oacc[mi][nt][2] * inv1);
            g_ctx[tok1 + col + 1] = tf32f(oacc[mi][nt][3] * inv1);
        }
    }
}

// ---------------- launch ------------------------------------------------------
extern "C" void kernel_launch(void* const* d_in, const int* in_sizes, int n_in,
                              void* d_out, int out_size)
{
    const float* x    = (const float*)d_in[0];
    const float* wqkv = (const float*)d_in[1];
    const float* bqkv = (const float*)d_in[2];
    const float* wo   = (const float*)d_in[3];
    const float* bo   = (const float*)d_in[4];
    float* out = (float*)d_out;

    cudaFuncSetAttribute(gemm_tf32<0>, cudaFuncAttributeMaxDynamicSharedMemorySize, GEMM_SMEM);
    cudaFuncSetAttribute(gemm_tf32<1>, cudaFuncAttributeMaxDynamicSharedMemorySize, GEMM_SMEM);
    cudaFuncSetAttribute(flash_attn,   cudaFuncAttributeMaxDynamicSharedMemorySize, SMEM_FLASH);

    float* xr; float* wqkvr; float* wor;
    cudaGetSymbolAddress((void**)&xr,    g_xr);
    cudaGetSymbolAddress((void**)&wqkvr, g_wqkvr);
    cudaGetSymbolAddress((void**)&wor,   g_wor);

    // 0) pre-round all GEMM operands to tf32
    round_copy<<<1024, 256>>>(x,    xr,    NTOK * NH / 4);
    round_copy<<<2048, 256>>>(wqkv, wqkvr, NH * 3 * NH / 4);
    round_copy<<<1024, 256>>>(wo,   wor,   NH * NH / 4);

    // 1) QKV GEMM + bias -> rounded (Q pre-scaled) Q/K/V in [b][h][s][d]
    gemm_tf32<0><<<dim3(3 * NH / 128, NTOK / 128), 128, GEMM_SMEM>>>(
        bqkv, nullptr, NTOK, 3 * NH, NH);

    // 2) flash attention -> rounded ctx (token-major)
    flash_attn<<<dim3(NS / 256, NB * NHEADS), 256, SMEM_FLASH>>>();

    // 3) output projection + bias -> final fp32 out
    gemm_tf32<1><<<dim3(NH / 128, NTOK / 128), 128, GEMM_SMEM>>>(
        bo, out, NTOK, NH, NH);
}